// round 5
// baseline (speedup 1.0000x reference)
#include <cuda_runtime.h>
#include <cuda_bf16.h>
#include <cstdint>
#include <math.h>

// ---------------- problem constants ----------------
#define BB 2048
#define KK 2048
#define HH 2048
#define FH 8192

// ---------------- GEMM config ----------------
#define BM 128
#define BN 128
#define BK 32              // bf16 K elems per chunk
#define NTH 256            // 8 warps: 2 (M) x 4 (N)
#define NCHUNK 128         // 2 phases * (2048/32)
#define ROWB 128           // smem row: hi[32]|lo[32] bf16 = 64B+64B
#define OFF_B 16384        // B tile offset within stage
#define STAGE_BYTES 32768
#define NSTAGE 3
#define SMEM_TOTAL (NSTAGE*STAGE_BYTES)

// ---------------- scratch (device globals; no alloc) ----------------
__device__ __align__(16) __nv_bfloat16 g_ah[2][(size_t)BB*KK];
__device__ __align__(16) __nv_bfloat16 g_al[2][(size_t)BB*KK];
__device__ __align__(16) __nv_bfloat16 g_wh[2][(size_t)FH*KK];
__device__ __align__(16) __nv_bfloat16 g_wl[2][(size_t)FH*KK];
__device__ __align__(16) float g_gates[(size_t)BB*FH];

// ---------------- PTX helpers (plain sm_100-safe) ----------------
__device__ __forceinline__ uint32_t smem_u32(const void* p) {
    return (uint32_t)__cvta_generic_to_shared(p);
}
__device__ __forceinline__ void cp16(uint32_t s, const void* g) {
    asm volatile("cp.async.cg.shared.global [%0], [%1], 16;"
                 :: "r"(s), "l"(__cvta_generic_to_global(g)) : "memory");
}
__device__ __forceinline__ void cp_commit() {
    asm volatile("cp.async.commit_group;" ::: "memory");
}
template <int N>
__device__ __forceinline__ void cp_wait() {
    asm volatile("cp.async.wait_group %0;" :: "n"(N) : "memory");
}
__device__ __forceinline__ void ldsm4(uint32_t* r, uint32_t a) {
    asm volatile("ldmatrix.sync.aligned.m8n8.x4.shared.b16 {%0,%1,%2,%3}, [%4];"
                 : "=r"(r[0]), "=r"(r[1]), "=r"(r[2]), "=r"(r[3]) : "r"(a));
}
__device__ __forceinline__ void mma16816(float* c, const uint32_t* a, const uint32_t* b) {
    asm volatile(
        "mma.sync.aligned.m16n8k16.row.col.f32.bf16.bf16.f32 "
        "{%0,%1,%2,%3}, {%4,%5,%6,%7}, {%8,%9}, {%0,%1,%2,%3};"
        : "+f"(c[0]), "+f"(c[1]), "+f"(c[2]), "+f"(c[3])
        : "r"(a[0]), "r"(a[1]), "r"(a[2]), "r"(a[3]), "r"(b[0]), "r"(b[1]));
}
__device__ __forceinline__ uint32_t swz(uint32_t x) {   // SW128
    return x ^ ((x >> 3) & 0x70);
}

// ---------------- split fp32 -> bf16 hi/lo, fully vectorized ----------------
__device__ __forceinline__ uint32_t pack2(float a, float b, float* ra, float* rb) {
    __nv_bfloat16 ha = __float2bfloat16(a);
    __nv_bfloat16 hb = __float2bfloat16(b);
    *ra = a - __bfloat162float(ha);
    *rb = b - __bfloat162float(hb);
    __nv_bfloat162 p(ha, hb);
    return *(uint32_t*)&p;
}
__device__ __forceinline__ uint32_t pack2lo(float a, float b) {
    __nv_bfloat162 p(__float2bfloat16(a), __float2bfloat16(b));
    return *(uint32_t*)&p;
}
__global__ void split_kernel(const float4* __restrict__ src,
                             uint4* __restrict__ hi,
                             uint4* __restrict__ lo, int n8)
{
    int i = blockIdx.x * blockDim.x + threadIdx.x;
    if (i >= n8) return;
    float4 v0 = src[2 * i];
    float4 v1 = src[2 * i + 1];
    float r[8];
    uint4 H, L;
    H.x = pack2(v0.x, v0.y, &r[0], &r[1]);
    H.y = pack2(v0.z, v0.w, &r[2], &r[3]);
    H.z = pack2(v1.x, v1.y, &r[4], &r[5]);
    H.w = pack2(v1.z, v1.w, &r[6], &r[7]);
    L.x = pack2lo(r[0], r[1]);
    L.y = pack2lo(r[2], r[3]);
    L.z = pack2lo(r[4], r[5]);
    L.w = pack2lo(r[6], r[7]);
    hi[i] = H;
    lo[i] = L;
}

// ---------------- tile loader: one K-chunk (A 16KB + B 16KB) ----------------
__device__ __forceinline__ void load_chunk(int c, uint32_t stage, int m0, int n0, int tid)
{
    const int ph = c >> 6;
    const int k0 = (c & 63) * BK;
    const __nv_bfloat16* __restrict__ Ah = g_ah[ph];
    const __nv_bfloat16* __restrict__ Al = g_al[ph];
    const __nv_bfloat16* __restrict__ Wh = g_wh[ph];
    const __nv_bfloat16* __restrict__ Wl = g_wl[ph];

    #pragma unroll
    for (int j = 0; j < 4; ++j) {
        int idx = tid + j * NTH;
        int r = idx >> 3, cb = idx & 7;
        uint32_t so = swz((uint32_t)(r * ROWB + cb * 16));
        const __nv_bfloat16* src = (cb < 4)
            ? Ah + (size_t)(m0 + r) * KK + k0 + (cb & 3) * 8
            : Al + (size_t)(m0 + r) * KK + k0 + (cb & 3) * 8;
        cp16(stage + so, src);
    }
    #pragma unroll
    for (int j = 0; j < 4; ++j) {
        int idx = tid + j * NTH;
        int r = idx >> 3, cb = idx & 7;
        uint32_t so = swz((uint32_t)(r * ROWB + cb * 16));
        const __nv_bfloat16* src = (cb < 4)
            ? Wh + (size_t)(n0 + r) * KK + k0 + (cb & 3) * 8
            : Wl + (size_t)(n0 + r) * KK + k0 + (cb & 3) * 8;
        cp16(stage + OFF_B + so, src);
    }
}

// ---------------- split-bf16 mma.sync GEMM ----------------
__global__ __launch_bounds__(NTH, 2)
void lstm_gemm_mma(float* __restrict__ gates)
{
    extern __shared__ __align__(1024) char smem[];
    const uint32_t sb = smem_u32(smem);
    const int tid = threadIdx.x;
    const int wid = tid >> 5;
    const int l   = tid & 31;
    const int m0  = blockIdx.y * BM;
    const int n0  = blockIdx.x * BN;
    const int wm  = wid & 1;
    const int wn  = wid >> 1;

    float acc[4][4][4];
    #pragma unroll
    for (int mt = 0; mt < 4; ++mt)
        #pragma unroll
        for (int nt = 0; nt < 4; ++nt)
            #pragma unroll
            for (int q = 0; q < 4; ++q) acc[mt][nt][q] = 0.0f;

    // Tile-relative swizzled ldmatrix offsets; per-ks (+32B) applied by XOR.
    uint32_t swzA[4][2];
    #pragma unroll
    for (int mt = 0; mt < 4; ++mt) {
        int r = wm * 64 + mt * 16 + (l & 15);
        #pragma unroll
        for (int hl = 0; hl < 2; ++hl)
            swzA[mt][hl] = swz((uint32_t)(r * ROWB + hl * 64 + (l >> 4) * 16));
    }
    uint32_t swzB[2][2];
    #pragma unroll
    for (int np = 0; np < 2; ++np) {
        int r = wn * 32 + np * 16 + ((l >> 4) << 3) + (l & 7);
        #pragma unroll
        for (int hl = 0; hl < 2; ++hl)
            swzB[np][hl] = OFF_B +
                swz((uint32_t)(r * ROWB + hl * 64 + ((l >> 3) & 1) * 16));
    }

    // prologue: 3 stages in flight
    load_chunk(0, sb, m0, n0, tid);
    cp_commit();
    load_chunk(1, sb + STAGE_BYTES, m0, n0, tid);
    cp_commit();
    load_chunk(2, sb + 2 * STAGE_BYTES, m0, n0, tid);
    cp_commit();

    for (int c = 0; c < NCHUNK; ++c) {
        const uint32_t base = sb + (uint32_t)(c % NSTAGE) * STAGE_BYTES;

        cp_wait<2>();          // chunk c resident (c+1, c+2 in flight)
        __syncthreads();

        #pragma unroll
        for (int ks = 0; ks < 2; ++ks) {
            const uint32_t kx = (uint32_t)ks << 5;
            uint32_t bh[2][4], bl[2][4];
            #pragma unroll
            for (int np = 0; np < 2; ++np) {
                ldsm4(bh[np], base + (swzB[np][0] ^ kx));
                ldsm4(bl[np], base + (swzB[np][1] ^ kx));
            }
            // A-fragment double buffer; product-major MMA order:
            // same-acc reuse distance = 4 MMAs (vs 1 before).
            uint32_t ah[2][4], al[2][4];
            ldsm4(ah[0], base + (swzA[0][0] ^ kx));
            ldsm4(al[0], base + (swzA[0][1] ^ kx));
            #pragma unroll
            for (int mt = 0; mt < 4; ++mt) {
                const int cur = mt & 1, nxt = cur ^ 1;
                if (mt < 3) {
                    ldsm4(ah[nxt], base + (swzA[mt + 1][0] ^ kx));
                    ldsm4(al[nxt], base + (swzA[mt + 1][1] ^ kx));
                }
                #pragma unroll
                for (int nt = 0; nt < 4; ++nt)
                    mma16816(acc[mt][nt], ah[cur], &bh[nt >> 1][(nt & 1) * 2]);
                #pragma unroll
                for (int nt = 0; nt < 4; ++nt)
                    mma16816(acc[mt][nt], ah[cur], &bl[nt >> 1][(nt & 1) * 2]);
                #pragma unroll
                for (int nt = 0; nt < 4; ++nt)
                    mma16816(acc[mt][nt], al[cur], &bh[nt >> 1][(nt & 1) * 2]);
            }
        }

        __syncthreads();       // all warps done reading stage c%NSTAGE
        if (c + NSTAGE < NCHUNK)
            load_chunk(c + NSTAGE, base, m0, n0, tid);
        cp_commit();           // fixed group accounting
    }

    // epilogue: fragments -> gates
    const int rbase = m0 + wm * 64 + (l >> 2);
    const int cbase = n0 + wn * 32 + 2 * (l & 3);
    #pragma unroll
    for (int mt = 0; mt < 4; ++mt) {
        #pragma unroll
        for (int nt = 0; nt < 4; ++nt) {
            const int r = rbase + mt * 16;
            const int cc = cbase + nt * 8;
            float2 v0 = make_float2(acc[mt][nt][0], acc[mt][nt][1]);
            float2 v1 = make_float2(acc[mt][nt][2], acc[mt][nt][3]);
            *(float2*)&gates[(size_t)r * FH + cc]       = v0;
            *(float2*)&gates[(size_t)(r + 8) * FH + cc] = v1;
        }
    }
}

// ---------------- pointwise LSTM epilogue (bias folded in) ----------------
__device__ __forceinline__ float sigmoidf_(float v) { return 1.0f / (1.0f + expf(-v)); }

__global__ void lstm_pointwise(const float* __restrict__ gates,
                               const float* __restrict__ Cprev,
                               const float* __restrict__ bih,
                               const float* __restrict__ bhh,
                               float* __restrict__ out)
{
    const int i4 = blockIdx.x * blockDim.x + threadIdx.x;
    const int total4 = BB * HH / 4;
    if (i4 >= total4) return;

    const int m = i4 / (HH / 4);
    const int n = (i4 % (HH / 4)) * 4;

    const float* __restrict__ grow = gates + (size_t)m * FH;
    float4 gi = *(const float4*)(grow + n);
    float4 gf = *(const float4*)(grow + HH + n);
    float4 gg = *(const float4*)(grow + 2 * HH + n);
    float4 go = *(const float4*)(grow + 3 * HH + n);

    float4 b0a = *(const float4*)(bih + n);
    float4 b0b = *(const float4*)(bhh + n);
    float4 b1a = *(const float4*)(bih + HH + n);
    float4 b1b = *(const float4*)(bhh + HH + n);
    float4 b2a = *(const float4*)(bih + 2 * HH + n);
    float4 b2b = *(const float4*)(bhh + 2 * HH + n);
    float4 b3a = *(const float4*)(bih + 3 * HH + n);
    float4 b3b = *(const float4*)(bhh + 3 * HH + n);

    float4 C = *(const float4*)(Cprev + (size_t)m * HH + n);

    float4 vh, vC, vf, vi, vg, vo;
    float* pgi = &gi.x; float* pgf = &gf.x; float* pgg = &gg.x; float* pgo = &go.x;
    float* pb0a = &b0a.x; float* pb0b = &b0b.x; float* pb1a = &b1a.x; float* pb1b = &b1b.x;
    float* pb2a = &b2a.x; float* pb2b = &b2b.x; float* pb3a = &b3a.x; float* pb3b = &b3b.x;
    float* pC = &C.x;
    float* ph = &vh.x; float* pc = &vC.x; float* pf = &vf.x; float* pi = &vi.x;
    float* pg = &vg.x; float* po = &vo.x;

    #pragma unroll
    for (int q = 0; q < 4; ++q) {
        float ig = sigmoidf_(pgi[q] + pb0a[q] + pb0b[q]);
        float fg = sigmoidf_(pgf[q] + pb1a[q] + pb1b[q]);
        float cg = tanhf(pgg[q] + pb2a[q] + pb2b[q]);
        float og = sigmoidf_(pgo[q] + pb3a[q] + pb3b[q]);
        float nC = fg * pC[q] + ig * cg;
        pf[q] = fg; pi[q] = ig; pg[q] = cg; po[q] = og;
        pc[q] = nC;
        ph[q] = og * tanhf(nC);
    }

    const size_t S = (size_t)BB * HH;
    const size_t idx = (size_t)m * HH + n;
    *(float4*)(out + idx)         = vh;
    *(float4*)(out + S + idx)     = vC;
    *(float4*)(out + 2 * S + idx) = vf;
    *(float4*)(out + 3 * S + idx) = vi;
    *(float4*)(out + 4 * S + idx) = vg;
    *(float4*)(out + 5 * S + idx) = vo;
}

// ---------------- launch ----------------
extern "C" void kernel_launch(void* const* d_in, const int* in_sizes, int n_in,
                              void* d_out, int out_size)
{
    const float* x     = (const float*)d_in[0];
    const float* hprev = (const float*)d_in[1];
    const float* Cprev = (const float*)d_in[2];
    const float* Wih   = (const float*)d_in[3];
    const float* bih   = (const float*)d_in[4];
    const float* Whh   = (const float*)d_in[5];
    const float* bhh   = (const float*)d_in[6];
    float* out = (float*)d_out;

    __nv_bfloat16 *ah, *al, *wh, *wl;
    float* gates;
    cudaGetSymbolAddress((void**)&ah, g_ah);
    cudaGetSymbolAddress((void**)&al, g_al);
    cudaGetSymbolAddress((void**)&wh, g_wh);
    cudaGetSymbolAddress((void**)&wl, g_wl);
    cudaGetSymbolAddress((void**)&gates, g_gates);

    static bool attr_set = false;
    if (!attr_set) {
        cudaFuncSetAttribute(lstm_gemm_mma,
                             cudaFuncAttributeMaxDynamicSharedMemorySize, SMEM_TOTAL);
        attr_set = true;
    }

    const int nA8 = BB * KK / 8;      // 524288
    const int nW8 = FH * KK / 8;      // 2097152
    const size_t A = (size_t)BB * KK;
    const size_t W = (size_t)FH * KK;

    split_kernel<<<(nA8 + 255) / 256, 256>>>((const float4*)x,
        (uint4*)ah, (uint4*)al, nA8);
    split_kernel<<<(nA8 + 255) / 256, 256>>>((const float4*)hprev,
        (uint4*)(ah + A), (uint4*)(al + A), nA8);
    split_kernel<<<(nW8 + 255) / 256, 256>>>((const float4*)Wih,
        (uint4*)wh, (uint4*)wl, nW8);
    split_kernel<<<(nW8 + 255) / 256, 256>>>((const float4*)Whh,
        (uint4*)(wh + W), (uint4*)(wl + W), nW8);

    dim3 grid(FH / BN, BB / BM);   // (64, 16)
    lstm_gemm_mma<<<grid, NTH, SMEM_TOTAL>>>(gates);

    const int total4 = BB * HH / 4;
    lstm_pointwise<<<(total4 + 255) / 256, 256>>>(gates, Cprev, bih, bhh, out);
}